// round 17
// baseline (speedup 1.0000x reference)
#include <cuda_runtime.h>
#include <math.h>

#define NBH     32
#define SLEN    8192
#define DIMC    128
#define NREG    96
#define NOUTC   32
#define TPB     128
#define NCHUNK  32
#define CHUNK_S 256

#define STRIDE  129                     // scr row stride; col 128 holds nrm
#define POFF    4624                    // pair P- offset (bank-disjoint)
#define MT_STR  100                     // rotT k-major row stride (16B-aligned)

#define OFF_M   (128 * STRIDE)          // 16512 ; M region 9600 floats
#define OFF_RO  (OFF_M + 9600)
#define OFF_SO  (OFF_RO + 1024)
#define OFF_CS  (OFF_SO + 1024)
#define OFF_UN  (OFF_CS + 96)           // union: invOrd (128 ints) + bits (768 ushort @ +512B)
#define SMEM_FLOATS (OFF_UN + 512)
#define SMEM_BYTES  (SMEM_FLOATS * 4)   // 115.07 KB -> 2 blocks/SM

typedef unsigned long long ull;
typedef unsigned short ushort;

__device__ float g_partial[NBH * NCHUNK * DIMC];
__device__ int   g_order[NBH * DIMC];
__device__ float g_colR[NREG];

__device__ __forceinline__ ull pack2(float lo, float hi)
{ ull r; asm("mov.b64 %0, {%1, %2};" : "=l"(r) : "f"(lo), "f"(hi)); return r; }
__device__ __forceinline__ void unpack2(ull p, float& lo, float& hi)
{ asm("mov.b64 {%0, %1}, %2;" : "=f"(lo), "=f"(hi) : "l"(p)); }
__device__ __forceinline__ ull fma2(ull a, ull b, ull c)
{ ull d; asm("fma.rn.f32x2 %0, %1, %2, %3;" : "=l"(d) : "l"(a), "l"(b), "l"(c)); return d; }
__device__ __forceinline__ ull mul2(ull a, ull b)
{ ull d; asm("mul.rn.f32x2 %0, %1, %2;" : "=l"(d) : "l"(a), "l"(b)); return d; }

__global__ void __launch_bounds__(DIMC) k_chnorm(const float* __restrict__ x)
{
    int bh = blockIdx.y, ck = blockIdx.x, c = threadIdx.x;
    const float* p = x + ((size_t)bh * SLEN + (size_t)ck * CHUNK_S) * DIMC + c;
    float acc = 0.f;
#pragma unroll 16
    for (int s = 0; s < CHUNK_S; ++s) {
        float t = p[(size_t)s * DIMC];
        acc = fmaf(t, t, acc);
    }
    g_partial[(bh * NCHUNK + ck) * DIMC + c] = acc;
}

__global__ void __launch_bounds__(DIMC) k_order(const float* __restrict__ rotR)
{
    if (blockIdx.x == NBH) {
        int j = threadIdx.x;
        if (j < NREG) {
            float a = 0.f;
            for (int i = 0; i < NREG; ++i) a += rotR[i * NREG + j];
            g_colR[j] = a;
        }
        return;
    }
    __shared__ float nsq[DIMC];
    __shared__ int   flag[DIMC];
    int bh = blockIdx.x, c = threadIdx.x;
    float a = 0.f;
    for (int k = 0; k < NCHUNK; ++k) a += g_partial[(bh * NCHUNK + k) * DIMC + c];
    nsq[c] = a;
    __syncthreads();
    int rank = 0;
    for (int d = 0; d < DIMC; ++d) {
        float nd = nsq[d];
        rank += (nd > a) || (nd == a && d < c);
    }
    int isout = (rank < NOUTC) ? 1 : 0;
    flag[c] = isout;
    __syncthreads();
    int pos = 0;
    for (int d = 0; d < c; ++d) pos += (flag[d] == isout);
    g_order[bh * DIMC + (isout ? (NREG + pos) : pos)] = c;
}

__global__ void __launch_bounds__(TPB, 2) k_main(
    const float* __restrict__ x,
    const float* __restrict__ rotR, const float* __restrict__ rotO,
    const float* __restrict__ cbR,  const float* __restrict__ cbO,
    const float* __restrict__ SR,   const float* __restrict__ SO,
    float* __restrict__ out)
{
    extern __shared__ float sh[];
    float*  scr    = sh;
    float*  shM    = sh + OFF_M;
    float*  shRo   = sh + OFF_RO;
    float*  shSo   = sh + OFF_SO;
    float*  shCs   = sh + OFF_CS;
    int*    invOrd = (int*)(sh + OFF_UN);
    ushort* bits   = (ushort*)(sh + OFF_UN + 128);

    const int bh  = blockIdx.y;
    const int tid = threadIdx.x;
    const size_t rowBase = (size_t)bh * SLEN + (size_t)blockIdx.x * TPB;
    const float4* xv   = (const float4*)(x   + rowBase * DIMC);
    float4*       outv = (float4*)      (out + rowBase * DIMC);

    // invOrd
    { int ch = g_order[bh * DIMC + tid]; invOrd[ch] = tid; }
    __syncthreads();

    // stage x gathered; rotT k-major; small matrices; colsums
#pragma unroll 4
    for (int i = tid; i < TPB * 32; i += TPB) {
        float4 t = xv[i];
        int row = i >> 5, c4 = (i & 31) * 4;
        float* b = scr + row * STRIDE;
        b[invOrd[c4 + 0]] = t.x;
        b[invOrd[c4 + 1]] = t.y;
        b[invOrd[c4 + 2]] = t.z;
        b[invOrd[c4 + 3]] = t.w;
    }
    for (int idx = tid; idx < NREG * NREG; idx += TPB) {
        int i = idx / NREG, j = idx - i * NREG;     // i = out, j = k
        shM[j * MT_STR + i] = rotR[idx];
    }
    for (int i = tid; i < NOUTC * NOUTC; i += TPB) { shRo[i] = rotO[i]; shSo[i] = SO[i]; }
    if (tid < NREG) shCs[tid] = g_colR[tid];
    __syncthreads();

    // norms -> scr col 128
    {
        const float* m = scr + tid * STRIDE;
        ull n2 = 0ull;
#pragma unroll
        for (int q = 0; q < 48; ++q) {
            ull t = pack2(m[2 * q], m[2 * q + 1]);
            n2 = fma2(t, t, n2);
        }
        float nl, nh;
        unpack2(n2, nl, nh);
        scr[tid * STRIDE + 128] = fmaxf(sqrtf(nl + nh), 1e-8f);
    }
    __syncthreads();

    const float cR0 = __ldg(cbR), cR1 = __ldg(cbR + 1);
    const float midR = 0.5f * (cR0 + cR1);
    const float cO0 = __ldg(cbO), cO1 = __ldg(cbO + 1), cO2 = __ldg(cbO + 2), cO3 = __ldg(cbO + 3);
    const float mO0 = 0.5f * (cO0 + cO1), mO1 = 0.5f * (cO1 + cO2), mO2 = 0.5f * (cO2 + cO3);
    const float SCALE_R = 1.2533141373155003f / 96.0f;
    const float SCALE_O = 1.2533141373155003f / 32.0f;
    const ull onep    = pack2(1.f, 1.f);
    const ull negonep = pack2(-1.f, -1.f);
    const float chalf = 0.5f * (cR1 - cR0);
    const ull cmidp   = pack2(midR, midR);
    const ull chalfp  = pack2(chalf, chalf);

    // ---- GEMM pass 1 (96 threads): rows rg*8..+7, outs og*16..+15 ----
    if (tid < 96) {
        const int rg = tid / 6, og = tid - (tid / 6) * 6;
        ull acc[8][8];
#pragma unroll
        for (int r = 0; r < 8; ++r)
#pragma unroll
            for (int p = 0; p < 8; ++p) acc[r][p] = 0ull;
#pragma unroll 1
        for (int k = 0; k < NREG; ++k) {
            const ulonglong2* mr = (const ulonglong2*)(shM + k * MT_STR + og * 16);
            ulonglong2 q0 = mr[0], q1 = mr[1], q2 = mr[2], q3 = mr[3];
            const float* xb = scr + (rg * 8) * STRIDE + k;
#pragma unroll
            for (int r = 0; r < 8; ++r) {
                float xs = xb[r * STRIDE];
                ull xx = pack2(xs, xs);
                acc[r][0] = fma2(q0.x, xx, acc[r][0]);
                acc[r][1] = fma2(q0.y, xx, acc[r][1]);
                acc[r][2] = fma2(q1.x, xx, acc[r][2]);
                acc[r][3] = fma2(q1.y, xx, acc[r][3]);
                acc[r][4] = fma2(q2.x, xx, acc[r][4]);
                acc[r][5] = fma2(q2.y, xx, acc[r][5]);
                acc[r][6] = fma2(q3.x, xx, acc[r][6]);
                acc[r][7] = fma2(q3.y, xx, acc[r][7]);
            }
        }
#pragma unroll
        for (int r = 0; r < 8; ++r) {
            int row = rg * 8 + r;
            float inv = 1.0f / scr[row * STRIDE + 128];
            unsigned b16 = 0u;
#pragma unroll
            for (int p = 0; p < 8; ++p) {
                float a, b;
                unpack2(acc[r][p], a, b);
                b16 |= (unsigned)(a * inv > midR) << (2 * p);
                b16 |= (unsigned)(b * inv > midR) << (2 * p + 1);
            }
            bits[row * 6 + og] = (ushort)b16;
        }
    }
    __syncthreads();

    // rebuild shM as rot pair form (overwrites rotT)
#pragma unroll 4
    for (int k = 0; k < 36; ++k) {
        int idx = tid + k * TPB;
        int P = idx / NREG, j = idx - P * NREG;
        float a = __ldg(rotR + (2 * P) * NREG + j);
        float b = __ldg(rotR + (2 * P + 1) * NREG + j);
        shM[P * NREG + j]        = a + b;
        shM[POFF + P * NREG + j] = a - b;
    }
    __syncthreads();

    float* myscr = scr + tid * STRIDE;
    float nrm = myscr[128];
    const ull nrmp = pack2(nrm, nrm);

    // gather vp (contiguous) + read codes
    ull vp[48];
#pragma unroll
    for (int p = 0; p < 48; ++p) vp[p] = pack2(myscr[2 * p], myscr[2 * p + 1]);
    unsigned sb0 = (unsigned)bits[tid * 6 + 0] | ((unsigned)bits[tid * 6 + 1] << 16);
    unsigned sb1 = (unsigned)bits[tid * 6 + 2] | ((unsigned)bits[tid * 6 + 3] << 16);
    unsigned sb2 = (unsigned)bits[tid * 6 + 4] | ((unsigned)bits[tid * 6 + 5] << 16);

    // pass 2 (champion)
    ull rsq2 = 0ull;
#pragma unroll
    for (int jg = 0; jg < NREG; jg += 32) {
        ull A[16];
#pragma unroll
        for (int k = 0; k < 16; ++k) A[k] = 0ull;
#pragma unroll
        for (int wi = 0; wi < 3; ++wi) {
            unsigned w = (wi == 0) ? sb0 : ((wi == 1) ? sb1 : sb2);
            const float* bp = shM + (wi * 16) * NREG + jg;
#pragma unroll 2
            for (int p = 0; p < 16; ++p) {
                unsigned be = (w >> (2 * p)) & 1u;
                unsigned bx = ((w >> (2 * p)) ^ (w >> (2 * p + 1))) & 1u;
                const ulonglong2* src = (const ulonglong2*)(bx ? (bp + POFF) : bp);
                ull s2 = be ? onep : negonep;
#pragma unroll
                for (int t = 0; t < 8; ++t) {
                    ulonglong2 m = src[t];
                    A[2 * t]     = fma2(s2, m.x, A[2 * t]);
                    A[2 * t + 1] = fma2(s2, m.y, A[2 * t + 1]);
                }
                bp += NREG;
            }
        }
#pragma unroll
        for (int k = 0; k < 16; ++k) {
            ull cs2 = *(const ull*)(shCs + jg + 2 * k);
            ull t = mul2(cmidp, cs2);
            t = fma2(chalfp, A[k], t);
            ull xm2 = mul2(t, nrmp);
            ull r2 = fma2(xm2, negonep, vp[jg / 2 + k]);
            vp[jg / 2 + k] = r2;
            rsq2 = fma2(r2, r2, rsq2);
        }
    }
    float rl, rh;
    unpack2(rsq2, rl, rh);
    float rn = fmaxf(sqrtf(rl + rh), 1e-10f);

    // SR pair form
    __syncthreads();
#pragma unroll 4
    for (int k = 0; k < 36; ++k) {
        int idx = tid + k * TPB;
        int P = idx / NREG, j = idx - P * NREG;
        float a = __ldg(SR + (2 * P) * NREG + j);
        float b = __ldg(SR + (2 * P + 1) * NREG + j);
        shM[P * NREG + j]        = a + b;
        shM[POFF + P * NREG + j] = a - b;
    }
    __syncthreads();

    // pass 3 (champion pair form)
    unsigned gb0 = 0u, gb1 = 0u, gb2 = 0u;
#pragma unroll 1
    for (int ig = 0; ig < 24; ++ig) {
        const ulonglong2* rp0 = (const ulonglong2*)(shM + (2 * ig) * NREG);
        const ulonglong2* rm0 = (const ulonglong2*)(shM + POFF + (2 * ig) * NREG);
        const ulonglong2* rp1 = (const ulonglong2*)(shM + (2 * ig + 1) * NREG);
        const ulonglong2* rm1 = (const ulonglong2*)(shM + POFF + (2 * ig + 1) * NREG);
        ull a0 = 0ull, a1 = 0ull, a2 = 0ull, a3 = 0ull;
#pragma unroll
        for (int q = 0; q < 24; ++q) {
            ull v0 = vp[2 * q], v1 = vp[2 * q + 1];
            ulonglong2 m0 = rp0[q]; a0 = fma2(m0.x, v0, a0); a0 = fma2(m0.y, v1, a0);
            ulonglong2 m1 = rm0[q]; a1 = fma2(m1.x, v0, a1); a1 = fma2(m1.y, v1, a1);
            ulonglong2 m2 = rp1[q]; a2 = fma2(m2.x, v0, a2); a2 = fma2(m2.y, v1, a2);
            ulonglong2 m3 = rm1[q]; a3 = fma2(m3.x, v0, a3); a3 = fma2(m3.y, v1, a3);
        }
        float l0, h0, l1, h1, l2, h2, l3, h3;
        unpack2(a0, l0, h0); unpack2(a1, l1, h1);
        unpack2(a2, l2, h2); unpack2(a3, l3, h3);
        float U0 = l0 + h0, W0 = l1 + h1;
        float U1 = l2 + h2, W1 = l3 + h3;
        unsigned b =  (unsigned)((U0 + W0) >= 0.f)
                   | ((unsigned)((U0 - W0) >= 0.f) << 1)
                   | ((unsigned)((U1 + W1) >= 0.f) << 2)
                   | ((unsigned)((U1 - W1) >= 0.f) << 3);
        if      (ig < 8)  gb0 |= b << (ig * 4);
        else if (ig < 16) gb1 |= b << ((ig - 8) * 4);
        else              gb2 |= b << ((ig - 16) * 4);
    }

    // pass 4 (champion; contiguous RMW)
    {
        float cc = SCALE_R * rn;
        const ull ccp = pack2(cc, cc);
#pragma unroll
        for (int jg = 0; jg < NREG; jg += 32) {
            ull A[16];
#pragma unroll
            for (int k = 0; k < 16; ++k) A[k] = 0ull;
#pragma unroll
            for (int wi = 0; wi < 3; ++wi) {
                unsigned w = (wi == 0) ? gb0 : ((wi == 1) ? gb1 : gb2);
                const float* bp = shM + (wi * 16) * NREG + jg;
#pragma unroll 2
                for (int p = 0; p < 16; ++p) {
                    unsigned be = (w >> (2 * p)) & 1u;
                    unsigned bx = ((w >> (2 * p)) ^ (w >> (2 * p + 1))) & 1u;
                    const ulonglong2* src = (const ulonglong2*)(bx ? (bp + POFF) : bp);
                    ull s2 = be ? onep : negonep;
#pragma unroll
                    for (int t = 0; t < 8; ++t) {
                        ulonglong2 m = src[t];
                        A[2 * t]     = fma2(s2, m.x, A[2 * t]);
                        A[2 * t + 1] = fma2(s2, m.y, A[2 * t + 1]);
                    }
                    bp += NREG;
                }
            }
#pragma unroll
            for (int k = 0; k < 16; ++k) {
                int j = jg + 2 * k;
                ull xp2 = pack2(myscr[j], myscr[j + 1]);
                ull xm2 = fma2(vp[jg / 2 + k], negonep, xp2);
                ull t = fma2(ccp, A[k], xm2);
                float ol, oh;
                unpack2(t, ol, oh);
                myscr[j]     = ol;
                myscr[j + 1] = oh;
            }
        }
    }

    // ---------------- outlier subspace ----------------
    {
        ull vop[16];
        ull nsqo2 = 0ull;
#pragma unroll
        for (int p = 0; p < 16; ++p) {
            ull t = pack2(myscr[96 + 2 * p], myscr[97 + 2 * p]);
            vop[p] = t;
            nsqo2 = fma2(t, t, nsqo2);
        }
        float ol, oh;
        unpack2(nsqo2, ol, oh);
        float nrmo = fmaxf(sqrtf(ol + oh), 1e-8f);
        float invo = 1.0f / nrmo;
        const ull nrmop = pack2(nrmo, nrmo);

        unsigned code0 = 0u, code1 = 0u;
#pragma unroll 1
        for (int ig = 0; ig < 8; ++ig) {
            const ulonglong2* r0 = (const ulonglong2*)(shRo + (4 * ig + 0) * NOUTC);
            const ulonglong2* r1 = (const ulonglong2*)(shRo + (4 * ig + 1) * NOUTC);
            const ulonglong2* r2 = (const ulonglong2*)(shRo + (4 * ig + 2) * NOUTC);
            const ulonglong2* r3 = (const ulonglong2*)(shRo + (4 * ig + 3) * NOUTC);
            ull a0 = 0ull, a1 = 0ull, a2 = 0ull, a3 = 0ull;
#pragma unroll
            for (int q = 0; q < 8; ++q) {
                ull v0 = vop[2 * q], v1 = vop[2 * q + 1];
                ulonglong2 m0 = r0[q]; a0 = fma2(m0.x, v0, a0); a0 = fma2(m0.y, v1, a0);
                ulonglong2 m1 = r1[q]; a1 = fma2(m1.x, v0, a1); a1 = fma2(m1.y, v1, a1);
                ulonglong2 m2 = r2[q]; a2 = fma2(m2.x, v0, a2); a2 = fma2(m2.y, v1, a2);
                ulonglong2 m3 = r3[q]; a3 = fma2(m3.x, v0, a3); a3 = fma2(m3.y, v1, a3);
            }
            float l0, h0, l1, h1, l2, h2, l3, h3;
            unpack2(a0, l0, h0); unpack2(a1, l1, h1);
            unpack2(a2, l2, h2); unpack2(a3, l3, h3);
            float y0 = (l0 + h0) * invo, y1 = (l1 + h1) * invo;
            float y2 = (l2 + h2) * invo, y3 = (l3 + h3) * invo;
            unsigned i0 = (unsigned)(y0 > mO0) + (unsigned)(y0 > mO1) + (unsigned)(y0 > mO2);
            unsigned i1 = (unsigned)(y1 > mO0) + (unsigned)(y1 > mO1) + (unsigned)(y1 > mO2);
            unsigned i2 = (unsigned)(y2 > mO0) + (unsigned)(y2 > mO1) + (unsigned)(y2 > mO2);
            unsigned i3 = (unsigned)(y3 > mO0) + (unsigned)(y3 > mO1) + (unsigned)(y3 > mO2);
            unsigned b8 = i0 | (i1 << 2) | (i2 << 4) | (i3 << 6);
            if (ig < 4) code0 |= b8 << (ig * 8);
            else        code1 |= b8 << ((ig - 4) * 8);
        }

        ull xmo2[16];
        ull rsqo2 = 0ull;
        {
            ull A[16];
#pragma unroll
            for (int k = 0; k < 16; ++k) A[k] = 0ull;
#pragma unroll
            for (int wi = 0; wi < 2; ++wi) {
                unsigned w = (wi == 0) ? code0 : code1;
                const ulonglong2* mp = (const ulonglong2*)(shRo + (wi * 16) * NOUTC);
#pragma unroll 2
                for (int b = 0; b < 16; ++b) {
                    unsigned idx = (w >> (2 * b)) & 3u;
                    float lo = (idx & 1u) ? cO1 : cO0;
                    float hi = (idx & 1u) ? cO3 : cO2;
                    float yh = (idx & 2u) ? hi : lo;
                    ull yh2 = pack2(yh, yh);
#pragma unroll
                    for (int t = 0; t < 8; ++t) {
                        ulonglong2 m = mp[t];
                        A[2 * t]     = fma2(yh2, m.x, A[2 * t]);
                        A[2 * t + 1] = fma2(yh2, m.y, A[2 * t + 1]);
                    }
                    mp += NOUTC / 4;
                }
            }
#pragma unroll
            for (int k = 0; k < 16; ++k) {
                ull xm2 = mul2(A[k], nrmop);
                xmo2[k] = xm2;
                ull r2 = fma2(xm2, negonep, vop[k]);
                vop[k] = r2;
                rsqo2 = fma2(r2, r2, rsqo2);
            }
        }
        float sl, shh;
        unpack2(rsqo2, sl, shh);
        float rno = fmaxf(sqrtf(sl + shh), 1e-10f);

        unsigned gbo = 0u;
#pragma unroll 1
        for (int ig = 0; ig < 8; ++ig) {
            const ulonglong2* r0 = (const ulonglong2*)(shSo + (4 * ig + 0) * NOUTC);
            const ulonglong2* r1 = (const ulonglong2*)(shSo + (4 * ig + 1) * NOUTC);
            const ulonglong2* r2 = (const ulonglong2*)(shSo + (4 * ig + 2) * NOUTC);
            const ulonglong2* r3 = (const ulonglong2*)(shSo + (4 * ig + 3) * NOUTC);
            ull a0 = 0ull, a1 = 0ull, a2 = 0ull, a3 = 0ull;
#pragma unroll
            for (int q = 0; q < 8; ++q) {
                ull v0 = vop[2 * q], v1 = vop[2 * q + 1];
                ulonglong2 m0 = r0[q]; a0 = fma2(m0.x, v0, a0); a0 = fma2(m0.y, v1, a0);
                ulonglong2 m1 = r1[q]; a1 = fma2(m1.x, v0, a1); a1 = fma2(m1.y, v1, a1);
                ulonglong2 m2 = r2[q]; a2 = fma2(m2.x, v0, a2); a2 = fma2(m2.y, v1, a2);
                ulonglong2 m3 = r3[q]; a3 = fma2(m3.x, v0, a3); a3 = fma2(m3.y, v1, a3);
            }
            float l0, h0, l1, h1, l2, h2, l3, h3;
            unpack2(a0, l0, h0); unpack2(a1, l1, h1);
            unpack2(a2, l2, h2); unpack2(a3, l3, h3);
            unsigned b =  (unsigned)((l0 + h0) >= 0.f)
                       | ((unsigned)((l1 + h1) >= 0.f) << 1)
                       | ((unsigned)((l2 + h2) >= 0.f) << 2)
                       | ((unsigned)((l3 + h3) >= 0.f) << 3);
            gbo |= b << (ig * 4);
        }

        // outlier pass 4: sign-weighted sum over normal-form shSo
        {
            float cc = SCALE_O * rno;
            const ull ccp = pack2(cc, cc);
            ull A[16];
#pragma unroll
            for (int k = 0; k < 16; ++k) A[k] = 0ull;
#pragma unroll 2
            for (int b = 0; b < 32; ++b) {
                ull s2 = ((gbo >> b) & 1u) ? onep : negonep;
                const ulonglong2* mp = (const ulonglong2*)(shSo + b * NOUTC);
#pragma unroll
                for (int t = 0; t < 8; ++t) {
                    ulonglong2 m = mp[t];
                    A[2 * t]     = fma2(s2, m.x, A[2 * t]);
                    A[2 * t + 1] = fma2(s2, m.y, A[2 * t + 1]);
                }
            }
#pragma unroll
            for (int k = 0; k < 16; ++k) {
                ull t = fma2(ccp, A[k], xmo2[k]);
                float o0, o1;
                unpack2(t, o0, o1);
                myscr[96 + 2 * k] = o0;
                myscr[97 + 2 * k] = o1;
            }
        }
    }

    // copy-out: un-permute via invOrd (still intact in smem)
    __syncthreads();
#pragma unroll 4
    for (int i = tid; i < TPB * 32; i += TPB) {
        int row = i >> 5, c4 = (i & 31) * 4;
        const float* s = scr + row * STRIDE;
        outv[i] = make_float4(s[invOrd[c4 + 0]], s[invOrd[c4 + 1]],
                              s[invOrd[c4 + 2]], s[invOrd[c4 + 3]]);
    }
}

extern "C" void kernel_launch(void* const* d_in, const int* in_sizes, int n_in,
                              void* d_out, int out_size)
{
    const float* x    = (const float*)d_in[0];
    const float* rotR = (const float*)d_in[1];
    const float* rotO = (const float*)d_in[2];
    const float* cbR  = (const float*)d_in[3];
    const float* cbO  = (const float*)d_in[4];
    const float* SR   = (const float*)d_in[5];
    const float* SO   = (const float*)d_in[6];
    float* out = (float*)d_out;

    static int smem_set = 0;
    if (!smem_set) {
        cudaFuncSetAttribute(k_main, cudaFuncAttributeMaxDynamicSharedMemorySize, SMEM_BYTES);
        smem_set = 1;
    }

    dim3 gA(NCHUNK, NBH);
    k_chnorm<<<gA, DIMC>>>(x);
    k_order<<<NBH + 1, DIMC>>>(rotR);
    dim3 gM(SLEN / TPB, NBH);
    k_main<<<gM, TPB, SMEM_BYTES>>>(x, rotR, rotO, cbR, cbO, SR, SO, out);
}